// round 1
// baseline (speedup 1.0000x reference)
#include <cuda_runtime.h>
#include <cstdint>
#include <cstddef>

#define NN   384
#define DIN  128
#define HID  256
#define HID2 128

// ---------------- scratch (device globals: allocation-free) ----------------
__device__ float g_H0[NN * HID];                 // 384x256
__device__ float g_h3[NN * NN * HID2];           // 384x384x128 = 75.5 MB
__device__ float g_D [NN * HID2];                // h4[b,b,:]
__device__ float g_S [NN * NN];                  // supplement pre-tril

// ---------------- helpers ----------------
__device__ __forceinline__ uint32_t f2tf(float x) {
    uint32_t r;
    asm("cvt.rna.tf32.f32 %0, %1;" : "=r"(r) : "f"(x));
    return r;
}
__device__ __forceinline__ uint32_t asu(float x) { return __float_as_uint(x); }

__device__ __forceinline__ void mma_tf32(float* c, const uint32_t* a, const uint32_t* b) {
    asm volatile(
        "mma.sync.aligned.m16n8k8.row.col.f32.tf32.tf32.f32 "
        "{%0,%1,%2,%3}, {%4,%5,%6,%7}, {%8,%9}, {%0,%1,%2,%3};\n"
        : "+f"(c[0]), "+f"(c[1]), "+f"(c[2]), "+f"(c[3])
        : "r"(a[0]), "r"(a[1]), "r"(a[2]), "r"(a[3]), "r"(b[0]), "r"(b[1]));
}

// SMEM tile strides (padded for conflict-free mma fragment loads)
#define AS_STRIDE 36     // 128x32 A tile, stride 36: banks 4g+t4 -> conflict-free
#define BS_STRIDE 136    // 32x128 B tile, stride 136: banks 8k+g -> conflict-free
#define CS_STRIDE 260    // 128x256 staging, stride 260: banks 4g+t4 -> conflict-free
#define AS_BUF (128 * AS_STRIDE)   // 4608 floats
#define BS_BUF (32  * BS_STRIDE)   // 4352 floats

// 128x32 global tile -> regs (with tf32 round), row stride ldm
__device__ __forceinline__ void ldg_tileA(uint4 (&r)[4], const float* __restrict__ src,
                                          int ldm, int tid) {
#pragma unroll
    for (int i = 0; i < 4; i++) {
        int f = tid + 256 * i;
        int row = f >> 3, c4 = f & 7;
        float4 v = *(const float4*)(src + (size_t)row * ldm + c4 * 4);
        r[i].x = f2tf(v.x); r[i].y = f2tf(v.y); r[i].z = f2tf(v.z); r[i].w = f2tf(v.w);
    }
}
__device__ __forceinline__ void sts_tileA(float* As, const uint4 (&r)[4], int tid) {
#pragma unroll
    for (int i = 0; i < 4; i++) {
        int f = tid + 256 * i;
        int row = f >> 3, c4 = f & 7;
        *(uint4*)(As + row * AS_STRIDE + c4 * 4) = r[i];
    }
}
// 32x128 global tile -> regs, row stride ldm
__device__ __forceinline__ void ldg_tileB(uint4 (&r)[4], const float* __restrict__ src,
                                          int ldm, int tid) {
#pragma unroll
    for (int i = 0; i < 4; i++) {
        int f = tid + 256 * i;
        int row = f >> 5, c4 = f & 31;
        float4 v = *(const float4*)(src + (size_t)row * ldm + c4 * 4);
        r[i].x = f2tf(v.x); r[i].y = f2tf(v.y); r[i].z = f2tf(v.z); r[i].w = f2tf(v.w);
    }
}
__device__ __forceinline__ void sts_tileB(float* Bs, const uint4 (&r)[4], int tid) {
#pragma unroll
    for (int i = 0; i < 4; i++) {
        int f = tid + 256 * i;
        int row = f >> 5, c4 = f & 31;
        *(uint4*)(Bs + row * BS_STRIDE + c4 * 4) = r[i];
    }
}

// one 32-deep k-tile of the 128x128 warp-cooperative GEMM (warp grid 4m x 2n, warp tile 32x64)
__device__ __forceinline__ void compute_ktile(float (&c)[2][8][4],
                                              const float* __restrict__ As,
                                              const float* __restrict__ Bs,
                                              int rA, int cB, int g, int t4) {
#pragma unroll
    for (int kk = 0; kk < 4; kk++) {
        const int k = kk * 8;
        uint32_t a[2][4];
#pragma unroll
        for (int tm = 0; tm < 2; tm++) {
            const float* ap = As + (rA + tm * 16 + g) * AS_STRIDE + k + t4;
            a[tm][0] = asu(ap[0]);
            a[tm][1] = asu(ap[8 * AS_STRIDE]);
            a[tm][2] = asu(ap[4]);
            a[tm][3] = asu(ap[8 * AS_STRIDE + 4]);
        }
        uint32_t bb[8][2];
#pragma unroll
        for (int tn = 0; tn < 8; tn++) {
            const float* bp = Bs + (k + t4) * BS_STRIDE + cB + tn * 8 + g;
            bb[tn][0] = asu(bp[0]);
            bb[tn][1] = asu(bp[4 * BS_STRIDE]);
        }
#pragma unroll
        for (int tm = 0; tm < 2; tm++)
#pragma unroll
            for (int tn = 0; tn < 8; tn++)
                mma_tf32(c[tm][tn], a[tm], bb[tn]);
    }
}

// ---------------- kernel A: H0 = z @ W1[:128,:] ----------------
__global__ void k_h0(const float* __restrict__ z, const float* __restrict__ W1) {
    __shared__ float zs[DIN];
    int n = blockIdx.x, t = threadIdx.x;
    if (t < DIN) zs[t] = z[n * DIN + t];
    __syncthreads();
    float acc = 0.f;
#pragma unroll 8
    for (int d = 0; d < DIN; d++) acc += zs[d] * W1[d * HID + t];
    g_H0[n * HID + t] = acc;
}

// ---------------- kernel B: h3[b] tile = relu(P[b]@H0 + corr) @ W2 ----------------
__global__ void __launch_bounds__(256, 1)
k_h3(const float* __restrict__ P, const float* __restrict__ W1, const float* __restrict__ W2) {
    extern __shared__ float sm[];
    float* As   = sm;                          // 2 * 4608
    float* Bs   = As + 2 * AS_BUF;             // 2 * 4352
    float* Cs   = Bs + 2 * BS_BUF;             // 128 * 260 (relu'd h2 tile, tf32 bits)
    float* corr = Cs + 128 * CS_STRIDE;        // 128
    float* w1l  = corr + 128;                  // 256

    const int b = blockIdx.y, m0 = blockIdx.x * 128;
    const int tid = threadIdx.x, lane = tid & 31, wid = tid >> 5;
    const int wm = wid >> 1, wn = wid & 1, g = lane >> 2, t4 = lane & 3;
    const int rA = wm * 32, cB = wn * 64;
    const float* Pb = P + (size_t)b * NN * NN;

    if (tid < 128) corr[tid] = Pb[(size_t)(m0 + tid) * NN + b];
    w1l[tid] = W1[DIN * HID + tid];

    float cacc[2][8][4];
    uint4 ra[4], rb[4];

    // ---- phase 1: C1 = P_tile @ H0 chunk, relu+corr, stage to Cs ----
#pragma unroll 1
    for (int ch = 0; ch < 2; ch++) {
#pragma unroll
        for (int tm = 0; tm < 2; tm++)
#pragma unroll
            for (int tn = 0; tn < 8; tn++)
#pragma unroll
                for (int e = 0; e < 4; e++) cacc[tm][tn][e] = 0.f;

        ldg_tileA(ra, Pb + (size_t)m0 * NN, NN, tid);
        ldg_tileB(rb, g_H0 + ch * 128, HID, tid);
        sts_tileA(As, ra, tid);
        sts_tileB(Bs, rb, tid);
        __syncthreads();
#pragma unroll 1
        for (int kt = 0; kt < 12; kt++) {
            const int cur = kt & 1;
            if (kt < 11) {
                ldg_tileA(ra, Pb + (size_t)m0 * NN + (kt + 1) * 32, NN, tid);
                ldg_tileB(rb, g_H0 + (size_t)(kt + 1) * 32 * HID + ch * 128, HID, tid);
            }
            compute_ktile(cacc, As + cur * AS_BUF, Bs + cur * BS_BUF, rA, cB, g, t4);
            __syncthreads();
            if (kt < 11) {
                sts_tileA(As + (cur ^ 1) * AS_BUF, ra, tid);
                sts_tileB(Bs + (cur ^ 1) * BS_BUF, rb, tid);
                __syncthreads();
            }
        }
        // epilogue: relu(C1 + corr[m]*W1_last[h]) -> Cs (tf32 bits)
#pragma unroll
        for (int tm = 0; tm < 2; tm++) {
            int r0 = rA + tm * 16 + g;
            float cr0 = corr[r0], cr1 = corr[r0 + 8];
#pragma unroll
            for (int tn = 0; tn < 8; tn++) {
                int c0 = cB + tn * 8 + 2 * t4;
                float w0 = w1l[ch * 128 + c0], w1 = w1l[ch * 128 + c0 + 1];
                float v0 = fmaxf(cacc[tm][tn][0] + cr0 * w0, 0.f);
                float v1 = fmaxf(cacc[tm][tn][1] + cr0 * w1, 0.f);
                float v2 = fmaxf(cacc[tm][tn][2] + cr1 * w0, 0.f);
                float v3 = fmaxf(cacc[tm][tn][3] + cr1 * w1, 0.f);
                uint32_t* cp0 = (uint32_t*)(Cs + r0 * CS_STRIDE + ch * 128 + c0);
                cp0[0] = f2tf(v0); cp0[1] = f2tf(v1);
                uint32_t* cp1 = (uint32_t*)(Cs + (r0 + 8) * CS_STRIDE + ch * 128 + c0);
                cp1[0] = f2tf(v2); cp1[1] = f2tf(v3);
            }
        }
    }
    __syncthreads();

    // ---- phase 2: C2 = Cs(128x256) @ W2(256x128) ----
#pragma unroll
    for (int tm = 0; tm < 2; tm++)
#pragma unroll
        for (int tn = 0; tn < 8; tn++)
#pragma unroll
            for (int e = 0; e < 4; e++) cacc[tm][tn][e] = 0.f;

    ldg_tileB(rb, W2, HID2, tid);
    sts_tileB(Bs, rb, tid);
    __syncthreads();
#pragma unroll 1
    for (int kt = 0; kt < 8; kt++) {
        const int cur = kt & 1;
        if (kt < 7) ldg_tileB(rb, W2 + (size_t)(kt + 1) * 32 * HID2, HID2, tid);
#pragma unroll
        for (int kk = 0; kk < 4; kk++) {
            const int k = kt * 32 + kk * 8;
            uint32_t a[2][4];
#pragma unroll
            for (int tm = 0; tm < 2; tm++) {
                const float* ap = Cs + (rA + tm * 16 + g) * CS_STRIDE + k + t4;
                a[tm][0] = asu(ap[0]);
                a[tm][1] = asu(ap[8 * CS_STRIDE]);
                a[tm][2] = asu(ap[4]);
                a[tm][3] = asu(ap[8 * CS_STRIDE + 4]);
            }
            const float* Bc = Bs + cur * BS_BUF;
            uint32_t bb[8][2];
#pragma unroll
            for (int tn = 0; tn < 8; tn++) {
                const float* bp = Bc + ((k & 31) + t4) * BS_STRIDE + cB + tn * 8 + g;
                bb[tn][0] = asu(bp[0]);
                bb[tn][1] = asu(bp[4 * BS_STRIDE]);
            }
#pragma unroll
            for (int tm = 0; tm < 2; tm++)
#pragma unroll
                for (int tn = 0; tn < 8; tn++)
                    mma_tf32(cacc[tm][tn], a[tm], bb[tn]);
        }
        __syncthreads();
        if (kt < 7) {
            sts_tileB(Bs + (cur ^ 1) * BS_BUF, rb, tid);
            __syncthreads();
        }
    }
    // write h3 tile (fp32)
#pragma unroll
    for (int tm = 0; tm < 2; tm++) {
        int r0 = m0 + rA + tm * 16 + g;
#pragma unroll
        for (int tn = 0; tn < 8; tn++) {
            int c0 = cB + tn * 8 + 2 * t4;
            float* o0 = g_h3 + ((size_t)b * NN + r0) * HID2 + c0;
            o0[0] = cacc[tm][tn][0]; o0[1] = cacc[tm][tn][1];
            float* o1 = g_h3 + ((size_t)b * NN + r0 + 8) * HID2 + c0;
            o1[0] = cacc[tm][tn][2]; o1[1] = cacc[tm][tn][3];
        }
    }
}

// ---------------- kernel C0: D[b,:] = P[b][b,:] @ h3[b] (fp32) ----------------
__global__ void k_D(const float* __restrict__ P) {
    __shared__ float ps[NN];
    int b = blockIdx.x, t = threadIdx.x;  // 128 threads
    for (int k = t; k < NN; k += 128) ps[k] = P[(size_t)b * NN * NN + (size_t)b * NN + k];
    __syncthreads();
    float acc = 0.f;
#pragma unroll 4
    for (int k = 0; k < NN; k++) acc += ps[k] * g_h3[((size_t)b * NN + k) * HID2 + t];
    g_D[b * HID2 + t] = acc;
}

// ---------------- kernel C: S[b, j-tile] = (P[b]@h3[b]) . D[b] ----------------
__global__ void __launch_bounds__(256, 1)
k_S(const float* __restrict__ P) {
    extern __shared__ float sm[];
    float* As  = sm;                 // 2 * 4608
    float* Bs  = As + 2 * AS_BUF;    // 2 * 4352
    float* Ds  = Bs + 2 * BS_BUF;    // 128
    float* red = Ds + 128;           // 256

    const int b = blockIdx.y, j0 = blockIdx.x * 128;
    const int tid = threadIdx.x, lane = tid & 31, wid = tid >> 5;
    const int wm = wid >> 1, wn = wid & 1, g = lane >> 2, t4 = lane & 3;
    const int rA = wm * 32, cB = wn * 64;
    const float* Pb = P + (size_t)b * NN * NN;
    const float* h3b = g_h3 + (size_t)b * NN * HID2;

    if (tid < 128) Ds[tid] = g_D[b * HID2 + tid];

    float cacc[2][8][4];
#pragma unroll
    for (int tm = 0; tm < 2; tm++)
#pragma unroll
        for (int tn = 0; tn < 8; tn++)
#pragma unroll
            for (int e = 0; e < 4; e++) cacc[tm][tn][e] = 0.f;

    uint4 ra[4], rb[4];
    ldg_tileA(ra, Pb + (size_t)j0 * NN, NN, tid);
    ldg_tileB(rb, h3b, HID2, tid);
    sts_tileA(As, ra, tid);
    sts_tileB(Bs, rb, tid);
    __syncthreads();
#pragma unroll 1
    for (int kt = 0; kt < 12; kt++) {
        const int cur = kt & 1;
        if (kt < 11) {
            ldg_tileA(ra, Pb + (size_t)j0 * NN + (kt + 1) * 32, NN, tid);
            ldg_tileB(rb, h3b + (size_t)(kt + 1) * 32 * HID2, HID2, tid);
        }
        compute_ktile(cacc, As + cur * AS_BUF, Bs + cur * BS_BUF, rA, cB, g, t4);
        __syncthreads();
        if (kt < 11) {
            sts_tileA(As + (cur ^ 1) * AS_BUF, ra, tid);
            sts_tileB(Bs + (cur ^ 1) * BS_BUF, rb, tid);
            __syncthreads();
        }
    }
    // fused dot epilogue: S[b, j] = sum_c h4[j,c] * D[c]
#pragma unroll
    for (int tm = 0; tm < 2; tm++) {
        float p0 = 0.f, p1 = 0.f;
#pragma unroll
        for (int tn = 0; tn < 8; tn++) {
            int c0 = cB + tn * 8 + 2 * t4;
            float d0 = Ds[c0], d1 = Ds[c0 + 1];
            p0 += cacc[tm][tn][0] * d0 + cacc[tm][tn][1] * d1;
            p1 += cacc[tm][tn][2] * d0 + cacc[tm][tn][3] * d1;
        }
        p0 += __shfl_xor_sync(0xffffffffu, p0, 1);
        p0 += __shfl_xor_sync(0xffffffffu, p0, 2);
        p1 += __shfl_xor_sync(0xffffffffu, p1, 1);
        p1 += __shfl_xor_sync(0xffffffffu, p1, 2);
        if (t4 == 0) {
            red[wn * 128 + rA + tm * 16 + g]     = p0;
            red[wn * 128 + rA + tm * 16 + g + 8] = p1;
        }
    }
    __syncthreads();
    if (tid < 128) g_S[(size_t)b * NN + j0 + tid] = red[tid] + red[128 + tid];
}

// ---------------- kernel E: out = x + 0.5*(tril(S)+tril(S)^T) ----------------
__global__ void k_out(const float* __restrict__ x, float* __restrict__ out) {
    int idx = blockIdx.x * 256 + threadIdx.x;   // 147456 total
    int i = idx / NN, j = idx % NN;
    float s = (i > j) ? g_S[i * NN + j]
            : (i < j) ? g_S[j * NN + i]
                      : 2.f * g_S[i * NN + i];
    out[idx] = x[idx] + 0.5f * s;
}

// ---------------- launch ----------------
extern "C" void kernel_launch(void* const* d_in, const int* in_sizes, int n_in,
                              void* d_out, int out_size) {
    (void)in_sizes; (void)n_in; (void)out_size;
    const float* z  = (const float*)d_in[0];
    const float* x  = (const float*)d_in[1];
    const float* P  = (const float*)d_in[2];
    const float* W1 = (const float*)d_in[3];
    const float* W2 = (const float*)d_in[4];
    float* out = (float*)d_out;

    const int SMEM_B = (2 * AS_BUF + 2 * BS_BUF + 128 * CS_STRIDE + 128 + 256) * 4; // 206336
    const int SMEM_C = (2 * AS_BUF + 2 * BS_BUF + 128 + 256) * 4;                   // 73216

    cudaFuncSetAttribute(k_h3, cudaFuncAttributeMaxDynamicSharedMemorySize, SMEM_B);
    cudaFuncSetAttribute(k_S,  cudaFuncAttributeMaxDynamicSharedMemorySize, SMEM_C);

    k_h0<<<NN, 256>>>(z, W1);
    k_h3<<<dim3(3, NN), 256, SMEM_B>>>(P, W1, W2);
    k_D<<<NN, 128>>>(P);
    k_S<<<dim3(3, NN), 256, SMEM_C>>>(P);
    k_out<<<NN * NN / 256, 256>>>(x, out);
}

// round 4
// speedup vs baseline: 1.5428x; 1.5428x over previous
#include <cuda_runtime.h>
#include <cstdint>
#include <cstddef>

#define NN   384
#define DIN  128
#define HID  256
#define HID2 128

// ---------------- scratch (device globals: allocation-free) ----------------
__device__ float g_H0[NN * HID];                 // tf32-rounded z@W1[:128]
__device__ float g_A [NN * NN * HID];            // relu(P@H0 + corr) : 151 MB
__device__ float g_t3[NN * HID];                 // W2 (W2^T (A^T u)) per b
__device__ float g_S [NN * NN];                  // supplement pre-tril

// ---------------- helpers ----------------
__device__ __forceinline__ uint32_t f2tf(float x) {
    uint32_t r;
    asm("cvt.rna.tf32.f32 %0, %1;" : "=r"(r) : "f"(x));
    return r;
}
__device__ __forceinline__ uint32_t asu(float x) { return __float_as_uint(x); }

__device__ __forceinline__ void mma_tf32(float* c, const uint32_t* a, const uint32_t* b) {
    asm volatile(
        "mma.sync.aligned.m16n8k8.row.col.f32.tf32.tf32.f32 "
        "{%0,%1,%2,%3}, {%4,%5,%6,%7}, {%8,%9}, {%0,%1,%2,%3};\n"
        : "+f"(c[0]), "+f"(c[1]), "+f"(c[2]), "+f"(c[3])
        : "r"(a[0]), "r"(a[1]), "r"(a[2]), "r"(a[3]), "r"(b[0]), "r"(b[1]));
}

__device__ __forceinline__ void cpa16(uint32_t saddr, const void* gaddr) {
    asm volatile("cp.async.cg.shared.global [%0], [%1], 16;" :: "r"(saddr), "l"(gaddr));
}
__device__ __forceinline__ void cpa_commit() {
    asm volatile("cp.async.commit_group;");
}
template <int N>
__device__ __forceinline__ void cpa_wait() {
    asm volatile("cp.async.wait_group %0;" :: "n"(N));
}

#define AS_STRIDE 36
#define BS_STRIDE 136
#define AS_BUF (128 * AS_STRIDE)   // 4608 floats
#define BS_BUF (32  * BS_STRIDE)   // 4352 floats

// 128x32 tile global->smem via cp.async (raw bits)
__device__ __forceinline__ void cp_tileA(float* As, const float* __restrict__ src,
                                         int ldm, int tid) {
#pragma unroll
    for (int i = 0; i < 4; i++) {
        int f = tid + 256 * i;
        int row = f >> 3, c4 = f & 7;
        cpa16((uint32_t)__cvta_generic_to_shared(As + row * AS_STRIDE + c4 * 4),
              src + (size_t)row * ldm + c4 * 4);
    }
}
// 32x128 tile global->smem via cp.async
__device__ __forceinline__ void cp_tileB(float* Bs, const float* __restrict__ src,
                                         int ldm, int tid) {
#pragma unroll
    for (int i = 0; i < 4; i++) {
        int f = tid + 256 * i;
        int row = f >> 5, c4 = f & 31;
        cpa16((uint32_t)__cvta_generic_to_shared(Bs + row * BS_STRIDE + c4 * 4),
              src + (size_t)row * ldm + c4 * 4);
    }
}

// one 32-deep k-tile; A fragments get cvt.rna->tf32 (P arrives as raw fp32),
// B (H0) is pre-rounded so raw bits are already tf32.
__device__ __forceinline__ void compute_ktile(float (&c)[2][8][4],
                                              const float* __restrict__ As,
                                              const float* __restrict__ Bs,
                                              int rA, int cB, int g, int t4) {
#pragma unroll
    for (int kk = 0; kk < 4; kk++) {
        const int k = kk * 8;
        uint32_t a[2][4];
#pragma unroll
        for (int tm = 0; tm < 2; tm++) {
            const float* ap = As + (rA + tm * 16 + g) * AS_STRIDE + k + t4;
            a[tm][0] = f2tf(ap[0]);
            a[tm][1] = f2tf(ap[8 * AS_STRIDE]);
            a[tm][2] = f2tf(ap[4]);
            a[tm][3] = f2tf(ap[8 * AS_STRIDE + 4]);
        }
        uint32_t bb[8][2];
#pragma unroll
        for (int tn = 0; tn < 8; tn++) {
            const float* bp = Bs + (k + t4) * BS_STRIDE + cB + tn * 8 + g;
            bb[tn][0] = asu(bp[0]);
            bb[tn][1] = asu(bp[4 * BS_STRIDE]);
        }
#pragma unroll
        for (int tm = 0; tm < 2; tm++)
#pragma unroll
            for (int tn = 0; tn < 8; tn++)
                mma_tf32(c[tm][tn], a[tm], bb[tn]);
    }
}

// ---------------- kernel A0: H0 = tf32(z @ W1[:128,:]) ----------------
__global__ void k_h0(const float* __restrict__ z, const float* __restrict__ W1) {
    __shared__ float zs[DIN];
    int n = blockIdx.x, t = threadIdx.x;
    if (t < DIN) zs[t] = z[n * DIN + t];
    __syncthreads();
    float acc = 0.f;
#pragma unroll 8
    for (int d = 0; d < DIN; d++) acc += zs[d] * W1[d * HID + t];
    g_H0[n * HID + t] = __uint_as_float(f2tf(acc));
}

// ---------------- kernel A: A[b] = relu(P[b]@H0 + corr⊗w1l) ----------------
__global__ void __launch_bounds__(256, 2)
k_A(const float* __restrict__ P, const float* __restrict__ W1) {
    extern __shared__ float sm[];
    float* As   = sm;                     // 3 * 4608
    float* Bs   = As + 3 * AS_BUF;        // 3 * 4352
    float* corr = Bs + 3 * BS_BUF;        // 128
    float* w1l  = corr + 128;             // 128

    const int m0 = blockIdx.x * 128, n0 = blockIdx.y * 128, b = blockIdx.z;
    const int tid = threadIdx.x, lane = tid & 31, wid = tid >> 5;
    const int wm = wid >> 1, wn = wid & 1, g = lane >> 2, t4 = lane & 3;
    const int rA = wm * 32, cB = wn * 64;
    const float* Pb = P + (size_t)b * NN * NN;

    if (tid < 128) {
        corr[tid] = Pb[(size_t)(m0 + tid) * NN + b];
        w1l[tid]  = W1[DIN * HID + n0 + tid];
    }

    float cacc[2][8][4];
#pragma unroll
    for (int tm = 0; tm < 2; tm++)
#pragma unroll
        for (int tn = 0; tn < 8; tn++)
#pragma unroll
            for (int e = 0; e < 4; e++) cacc[tm][tn][e] = 0.f;

    // 3-stage cp.async pipeline over 12 k-tiles
    cp_tileA(As, Pb + (size_t)m0 * NN, NN, tid);
    cp_tileB(Bs, g_H0 + n0, HID, tid);
    cpa_commit();
    cp_tileA(As + AS_BUF, Pb + (size_t)m0 * NN + 32, NN, tid);
    cp_tileB(Bs + BS_BUF, g_H0 + 32 * HID + n0, HID, tid);
    cpa_commit();

#pragma unroll 1
    for (int kt = 0; kt < 12; kt++) {
        if (kt == 11) cpa_wait<0>(); else cpa_wait<1>();
        __syncthreads();
        if (kt < 10) {
            const int s = (kt + 2) % 3;
            cp_tileA(As + s * AS_BUF, Pb + (size_t)m0 * NN + (kt + 2) * 32, NN, tid);
            cp_tileB(Bs + s * BS_BUF, g_H0 + (size_t)(kt + 2) * 32 * HID + n0, HID, tid);
            cpa_commit();
        }
        const int cur = kt % 3;
        compute_ktile(cacc, As + cur * AS_BUF, Bs + cur * BS_BUF, rA, cB, g, t4);
    }

    // epilogue: relu(c + corr[m]*w1l[n]) -> g_A (fp32)
#pragma unroll
    for (int tm = 0; tm < 2; tm++) {
        int r0 = rA + tm * 16 + g;
        float cr0 = corr[r0], cr1 = corr[r0 + 8];
#pragma unroll
        for (int tn = 0; tn < 8; tn++) {
            int c0 = cB + tn * 8 + 2 * t4;
            float w0 = w1l[c0], w1 = w1l[c0 + 1];
            float* o0 = g_A + ((size_t)b * NN + m0 + r0) * HID + n0 + c0;
            o0[0] = fmaxf(cacc[tm][tn][0] + cr0 * w0, 0.f);
            o0[1] = fmaxf(cacc[tm][tn][1] + cr0 * w1, 0.f);
            float* o1 = g_A + ((size_t)b * NN + m0 + r0 + 8) * HID + n0 + c0;
            o1[0] = fmaxf(cacc[tm][tn][2] + cr1 * w0, 0.f);
            o1[1] = fmaxf(cacc[tm][tn][3] + cr1 * w1, 0.f);
        }
    }
}

// ---------------- kernel T: t3[b] = W2 (W2^T (A_b^T u_b)) (fp32 GEMV chain) ----------------
__global__ void k_t3(const float* __restrict__ P, const float* __restrict__ W2) {
    __shared__ float u[NN];
    __shared__ float t1s[HID];
    __shared__ float t2s[HID2];
    const int b = blockIdx.x, tid = threadIdx.x;  // 256 threads
    for (int k = tid; k < NN; k += 256)
        u[k] = P[(size_t)b * NN * NN + (size_t)b * NN + k];
    __syncthreads();

    // t1[h] = sum_k u[k] * A[b,k,h]   (coalesced across h)
    {
        float acc = 0.f;
        const float* Ab = g_A + (size_t)b * NN * HID + tid;
#pragma unroll 8
        for (int k = 0; k < NN; k++) acc += u[k] * Ab[(size_t)k * HID];
        t1s[tid] = acc;
    }
    __syncthreads();

    // t2[j] = sum_h W2[h,j] * t1[h]   (coalesced across j)
    if (tid < HID2) {
        float acc = 0.f;
#pragma unroll 8
        for (int h = 0; h < HID; h++) acc += W2[(size_t)h * HID2 + tid] * t1s[h];
        t2s[tid] = acc;
    }
    __syncthreads();

    // t3[h] = sum_j W2[h,j] * t2[j]
    {
        float acc = 0.f;
        const float* w2r = W2 + (size_t)tid * HID2;
#pragma unroll 8
        for (int j = 0; j < HID2; j++) acc += w2r[j] * t2s[j];
        g_t3[b * HID + tid] = acc;
    }
}

// ---------------- kernel V: v = A_b t3 ; S[b,:] = P[b] v (fp32) ----------------
__global__ void k_Sv(const float* __restrict__ P) {
    __shared__ float t3s[HID];
    __shared__ float vs[NN];
    const int b = blockIdx.x, tid = threadIdx.x;
    const int lane = tid & 31, wid = tid >> 5;   // 8 warps
    if (tid < HID) t3s[tid] = g_t3[b * HID + tid];
    __syncthreads();

    // v[r] = <A[b,r,:], t3>  — warp per row
    for (int r = wid; r < NN; r += 8) {
        const float* a = g_A + ((size_t)b * NN + r) * HID;
        float4 x0 = *(const float4*)(a + lane * 4);
        float4 x1 = *(const float4*)(a + 128 + lane * 4);
        float4 t0 = *(const float4*)(t3s + lane * 4);
        float4 t1 = *(const float4*)(t3s + 128 + lane * 4);
        float p = x0.x * t0.x + x0.y * t0.y + x0.z * t0.z + x0.w * t0.w
                + x1.x * t1.x + x1.y * t1.y + x1.z * t1.z + x1.w * t1.w;
#pragma unroll
        for (int o = 16; o > 0; o >>= 1) p += __shfl_xor_sync(0xffffffffu, p, o);
        if (lane == 0) vs[r] = p;
    }
    __syncthreads();

    // S[b,j] = <P[b,j,:], v>  — warp per row
    for (int j = wid; j < NN; j += 8) {
        const float* pr = P + (size_t)b * NN * NN + (size_t)j * NN;
        float p = 0.f;
#pragma unroll
        for (int c = 0; c < 3; c++) {
            float4 xv = *(const float4*)(pr + c * 128 + lane * 4);
            float4 vv = *(const float4*)(vs + c * 128 + lane * 4);
            p += xv.x * vv.x + xv.y * vv.y + xv.z * vv.z + xv.w * vv.w;
        }
#pragma unroll
        for (int o = 16; o > 0; o >>= 1) p += __shfl_xor_sync(0xffffffffu, p, o);
        if (lane == 0) g_S[(size_t)b * NN + j] = p;
    }
}

// ---------------- kernel E: out = x + 0.5*(tril(S)+tril(S)^T) ----------------
__global__ void k_out(const float* __restrict__ x, float* __restrict__ out) {
    int idx = blockIdx.x * 256 + threadIdx.x;   // 147456 total
    int i = idx / NN, j = idx % NN;
    float s = (i > j) ? g_S[i * NN + j]
            : (i < j) ? g_S[j * NN + i]
                      : 2.f * g_S[i * NN + i];
    out[idx] = x[idx] + 0.5f * s;
}

// ---------------- launch ----------------
extern "C" void kernel_launch(void* const* d_in, const int* in_sizes, int n_in,
                              void* d_out, int out_size) {
    (void)in_sizes; (void)n_in; (void)out_size;
    const float* z  = (const float*)d_in[0];
    const float* x  = (const float*)d_in[1];
    const float* P  = (const float*)d_in[2];
    const float* W1 = (const float*)d_in[3];
    const float* W2 = (const float*)d_in[4];
    float* out = (float*)d_out;

    const int SMEM_A = (3 * (AS_BUF + BS_BUF) + 256) * 4;   // 108,544 B

    cudaFuncSetAttribute(k_A, cudaFuncAttributeMaxDynamicSharedMemorySize, SMEM_A);

    k_h0<<<NN, 256>>>(z, W1);
    k_A<<<dim3(3, 2, NN), 256, SMEM_A>>>(P, W1);
    k_t3<<<NN, 256>>>(P, W2);
    k_Sv<<<NN, 256>>>(P);
    k_out<<<NN * NN / 256, 256>>>(x, out);
}